// round 16
// baseline (speedup 1.0000x reference)
#include <cuda_runtime.h>
#include <cuda_fp16.h>
#include <math.h>
#include <stdint.h>

#define BB 8
#define NSEQ 2048
#define DIM 512
#define MTOT (BB * NSEQ)

// Scratch (alloc-free rule: __device__ globals)
__device__ __half g_Xh[(size_t)MTOT * DIM];
__device__ __half g_Wh[(size_t)3 * DIM * DIM];
__device__ __half g_Qh[(size_t)MTOT * DIM];
__device__ __half g_Kh[(size_t)MTOT * DIM];
__device__ __half g_Vth[(size_t)BB * DIM * NSEQ];   // [b][d][n]
__device__ float  g_S[(size_t)BB * NSEQ * NSEQ];    // fp32 logits
__device__ __half g_P[(size_t)BB * NSEQ * NSEQ];    // fp16 probabilities

// ---------------------------------------------------------------------------
// helpers
// ---------------------------------------------------------------------------
__device__ __forceinline__ unsigned pk(float a, float b) {
    __half2 h = __floats2half2_rn(a, b);
    return *reinterpret_cast<unsigned*>(&h);
}
__device__ __forceinline__ uint32_t smem_u32(const void* p) {
    uint32_t a;
    asm("{ .reg .u64 t; cvta.to.shared.u64 t, %1; cvt.u32.u64 %0, t; }" : "=r"(a) : "l"(p));
    return a;
}
__device__ __forceinline__ void mma16(float c[4],
                                      unsigned a0, unsigned a1, unsigned a2, unsigned a3,
                                      unsigned b0, unsigned b1) {
    asm volatile(
        "mma.sync.aligned.m16n8k16.row.col.f32.f16.f16.f32 "
        "{%0,%1,%2,%3}, {%4,%5,%6,%7}, {%8,%9}, {%0,%1,%2,%3};"
        : "+f"(c[0]), "+f"(c[1]), "+f"(c[2]), "+f"(c[3])
        : "r"(a0), "r"(a1), "r"(a2), "r"(a3), "r"(b0), "r"(b1));
}
__device__ __forceinline__ void ldm_x4(unsigned& r0, unsigned& r1, unsigned& r2, unsigned& r3,
                                       uint32_t addr) {
    asm volatile("ldmatrix.sync.aligned.m8n8.x4.shared.b16 {%0,%1,%2,%3}, [%4];"
        : "=r"(r0), "=r"(r1), "=r"(r2), "=r"(r3) : "r"(addr));
}
__device__ __forceinline__ void cpa16(uint32_t dst, const void* src) {
    asm volatile("cp.async.ca.shared.global [%0], [%1], 16;" :: "r"(dst), "l"(src));
}
#define CP_COMMIT() asm volatile("cp.async.commit_group;" ::: "memory")
template<int N>
__device__ __forceinline__ void cp_wait() {
    asm volatile("cp.async.wait_group %0;" :: "n"(N) : "memory");
}

// ---------------------------------------------------------------------------
// GEMM NT: C(128x256 tile at (by,bx)) = A[M,K] * B[N,K]^T, fp16 in, fp32 acc.
// K_TILE = 64 halves -> 128B data rows padded to 144B (36 words).
// 4-stage cp.async pipeline, ONE __syncthreads per k-tile:
//   the sync that publishes stage kt also proves all warps finished reading
//   stage kt-1 (== (kt+3)%4), so the post-sync refill is WAR-safe.
// Warps 2(M) x 4(N), warp tile 64x64.
// ---------------------------------------------------------------------------
#define KT 64
#define ROWB 144
#define STAGE_BYTES (384 * ROWB)            // 55296
#define NSTAGE 4
#define DYN_SMEM (NSTAGE * STAGE_BYTES)     // 221184

__device__ __forceinline__ void fill_stage(uint32_t sb,
                                           const __half* __restrict__ A,
                                           const __half* __restrict__ B,
                                           int lda, int ldb, int tid)
{
#pragma unroll
    for (int it = 0; it < 4; it++) {           // A: 128 rows x 8 chunks
        const int cid = it * 256 + tid;
        const int row = cid >> 3, c = cid & 7;
        cpa16(sb + row * ROWB + c * 16, A + (size_t)row * lda + c * 8);
    }
#pragma unroll
    for (int it = 0; it < 8; it++) {           // B: 256 rows x 8 chunks
        const int cid = it * 256 + tid;
        const int row = cid >> 3, c = cid & 7;
        cpa16(sb + 128 * ROWB + row * ROWB + c * 16, B + (size_t)row * ldb + c * 8);
    }
}

__device__ __forceinline__ void gemm_nt_256(const __half* __restrict__ A,
                                            const __half* __restrict__ B,
                                            int lda, int ldb, int ktiles,
                                            float acc[4][8][4])
{
    extern __shared__ unsigned smdyn[];
    const uint32_t sb = smem_u32(smdyn);
    const int tid = threadIdx.x;

    A += (size_t)(blockIdx.y * 128) * lda;
    B += (size_t)(blockIdx.x * 256) * ldb;

    // prologue: 3 stages in flight (ktiles >= 3 for all call sites: 8 or 32)
    fill_stage(sb,                   A,          B,          lda, ldb, tid);
    CP_COMMIT();
    fill_stage(sb + STAGE_BYTES,     A + KT,     B + KT,     lda, ldb, tid);
    CP_COMMIT();
    fill_stage(sb + 2 * STAGE_BYTES, A + 2 * KT, B + 2 * KT, lda, ldb, tid);
    CP_COMMIT();

    const int lane = tid & 31;
    const int warp = tid >> 5;
    const int wm = (warp & 1) * 64;
    const int wn = (warp >> 1) * 64;
    const uint32_t lro = (uint32_t)((lane & 15) * ROWB + (lane >> 4) * 16);

#pragma unroll 1
    for (int kt = 0; kt < ktiles; kt++) {
        if (kt + 1 >= ktiles)      { cp_wait<0>(); }
        else if (kt + 2 >= ktiles) { cp_wait<1>(); }
        else                       { cp_wait<2>(); }
        __syncthreads();           // stage kt visible; stage kt-1 reads all done

        if (kt + 3 < ktiles) {     // refill stage (kt+3)%4 == (kt-1)%4 (WAR-safe)
            fill_stage(sb + ((kt + 3) % NSTAGE) * STAGE_BYTES,
                       A + (size_t)(kt + 3) * KT, B + (size_t)(kt + 3) * KT,
                       lda, ldb, tid);
            CP_COMMIT();
        }

        const uint32_t ab = sb + (kt % NSTAGE) * STAGE_BYTES;
        const uint32_t bb = ab + 128 * ROWB;
#pragma unroll
        for (int ks = 0; ks < 4; ks++) {
            unsigned af[4][4], bf[8][2];
#pragma unroll
            for (int i = 0; i < 4; i++)
                ldm_x4(af[i][0], af[i][1], af[i][2], af[i][3],
                       ab + (wm + i * 16) * ROWB + ks * 32 + lro);
#pragma unroll
            for (int jj = 0; jj < 4; jj++)
                ldm_x4(bf[2 * jj][0], bf[2 * jj + 1][0], bf[2 * jj][1], bf[2 * jj + 1][1],
                       bb + (wn + jj * 16) * ROWB + ks * 32 + lro);
#pragma unroll
            for (int i = 0; i < 4; i++)
#pragma unroll
                for (int j = 0; j < 8; j++)
                    mma16(acc[i][j], af[i][0], af[i][1], af[i][2], af[i][3],
                          bf[j][0], bf[j][1]);
        }
    }
    __syncthreads();               // protect smem reuse by caller epilogues
}

#define ACC_INIT(acc) \
    _Pragma("unroll") for (int i = 0; i < 4; i++) \
    _Pragma("unroll") for (int j = 0; j < 8; j++) \
    _Pragma("unroll") for (int v = 0; v < 4; v++) acc[i][j][v] = 0.f;

// ---------------------------------------------------------------------------
// Kernel 0a: fp32 -> fp16 convert (X)
// ---------------------------------------------------------------------------
__global__ void __launch_bounds__(256) cvt_kernel(const float* __restrict__ src,
                                                  __half* __restrict__ dst, int n4)
{
    const int i = blockIdx.x * 256 + threadIdx.x;
    if (i < n4) {
        const float4 f = ((const float4*)src)[i];
        ((uint2*)dst)[i] = make_uint2(pk(f.x, f.y), pk(f.z, f.w));
    }
}

// Kernel 0b: convert 3 weight matrices in one launch. grid (256, 3)
__global__ void __launch_bounds__(256) cvtw_kernel(const float* __restrict__ wq,
                                                   const float* __restrict__ wk,
                                                   const float* __restrict__ wv)
{
    const float* src = (blockIdx.y == 0) ? wq : (blockIdx.y == 1) ? wk : wv;
    __half* dst = g_Wh + (size_t)blockIdx.y * DIM * DIM;
    const int i = blockIdx.x * 256 + threadIdx.x;   // n4 = 65536 exactly
    const float4 f = ((const float4*)src)[i];
    ((uint2*)dst)[i] = make_uint2(pk(f.x, f.y), pk(f.z, f.w));
}

// ---------------------------------------------------------------------------
// Kernel 1: QKV projections. grid (DIM/256=2, MTOT/128=128, 3)
// z==2 (V): result is staged in smem and written TRANSPOSED to g_Vth only.
// ---------------------------------------------------------------------------
__global__ void __launch_bounds__(256, 1) proj_tc(
    const float* __restrict__ bq, const float* __restrict__ bk,
    const float* __restrict__ bv)
{
    const float* bias = (blockIdx.z == 0) ? bq : (blockIdx.z == 1) ? bk : bv;

    float acc[4][8][4];
    ACC_INIT(acc);
    gemm_nt_256(g_Xh, g_Wh + (size_t)blockIdx.z * DIM * DIM, DIM, DIM, DIM / KT, acc);

    const int tid  = threadIdx.x;
    const int lane = tid & 31;
    const int warp = tid >> 5;
    const int wm = (warp & 1) * 64;
    const int wn = (warp >> 1) * 64;
    const int grp = lane >> 2, tig = lane & 3;

    if (blockIdx.z < 2) {
        __half* C = (blockIdx.z == 0) ? g_Qh : g_Kh;
#pragma unroll
        for (int i = 0; i < 4; i++) {
            const int row = blockIdx.y * 128 + wm + i * 16 + grp;
#pragma unroll
            for (int j = 0; j < 8; j++) {
                const int col = blockIdx.x * 256 + wn + j * 8 + 2 * tig;
                const float b0 = bias[col], b1 = bias[col + 1];
                *(unsigned*)&C[(size_t)row * DIM + col] =
                    pk(acc[i][j][0] + b0, acc[i][j][1] + b1);
                *(unsigned*)&C[(size_t)(row + 8) * DIM + col] =
                    pk(acc[i][j][2] + b0, acc[i][j][3] + b1);
            }
        }
    } else {
        // V: transpose through smem (mainloop ended with __syncthreads)
        extern __shared__ unsigned smdyn[];
        __half* Ts = reinterpret_cast<__half*>(smdyn);   // [256 d][136 n-stride]
        const int b  = blockIdx.y / 16;                  // batch (16 y-blocks per batch)
        const int n0 = (blockIdx.y % 16) * 128;
        const int d0 = blockIdx.x * 256;
#pragma unroll
        for (int i = 0; i < 4; i++) {
            const int row = wm + i * 16 + grp;           // local n: 0..127
#pragma unroll
            for (int j = 0; j < 8; j++) {
                const int col = wn + j * 8 + 2 * tig;    // local d: 0..255
                const float b0 = bias[d0 + col], b1 = bias[d0 + col + 1];
                Ts[(col)     * 136 + row]     = __float2half(acc[i][j][0] + b0);
                Ts[(col + 1) * 136 + row]     = __float2half(acc[i][j][1] + b1);
                Ts[(col)     * 136 + row + 8] = __float2half(acc[i][j][2] + b0);
                Ts[(col + 1) * 136 + row + 8] = __float2half(acc[i][j][3] + b1);
            }
        }
        __syncthreads();
        // coalesced write-out: thread t owns d-row t (128 halves = 16 x uint4)
        __half* dst = g_Vth + (size_t)b * DIM * NSEQ + (size_t)(d0 + tid) * NSEQ + n0;
        const uint4* srow = reinterpret_cast<const uint4*>(Ts + (size_t)tid * 136);
#pragma unroll
        for (int i = 0; i < 16; i++)
            reinterpret_cast<uint4*>(dst)[i] = srow[i];
    }
}

// ---------------------------------------------------------------------------
// Kernel 3: scores = mask(QK^T / sqrt(D)) -> fp32 S. grid (8, 16, 8)
// ---------------------------------------------------------------------------
__global__ void __launch_bounds__(256, 1) scores_tc(const int* __restrict__ mask)
{
    const int b = blockIdx.z;
    float acc[4][8][4];
    ACC_INIT(acc);
    gemm_nt_256(g_Qh + (size_t)b * NSEQ * DIM, g_Kh + (size_t)b * NSEQ * DIM,
                DIM, DIM, DIM / KT, acc);

    const float scale = 0.04419417382415922f;  // 1/sqrt(512)
    const int lane = threadIdx.x & 31;
    const int warp = threadIdx.x >> 5;
    const int wm = (warp & 1) * 64;
    const int wn = (warp >> 1) * 64;
    const int grp = lane >> 2, tig = lane & 3;
    const int* mrow = mask + (size_t)b * NSEQ;
    float* C = g_S + (size_t)b * NSEQ * NSEQ;
#pragma unroll
    for (int i = 0; i < 4; i++) {
        const int row = blockIdx.y * 128 + wm + i * 16 + grp;
#pragma unroll
        for (int j = 0; j < 8; j++) {
            const int col = blockIdx.x * 256 + wn + j * 8 + 2 * tig;
            const bool k0 = (mrow[col] == 0);
            const bool k1 = (mrow[col + 1] == 0);
            const float v0 = k0 ? -1e9f : acc[i][j][0] * scale;
            const float v1 = k1 ? -1e9f : acc[i][j][1] * scale;
            const float v2 = k0 ? -1e9f : acc[i][j][2] * scale;
            const float v3 = k1 ? -1e9f : acc[i][j][3] * scale;
            *(float2*)&C[(size_t)row * NSEQ + col]       = make_float2(v0, v1);
            *(float2*)&C[(size_t)(row + 8) * NSEQ + col] = make_float2(v2, v3);
        }
    }
}

// ---------------------------------------------------------------------------
// Kernel 4: row softmax fp32 S -> fp16 P. One block (256 thr) per row. float4 IO.
// ---------------------------------------------------------------------------
__global__ void __launch_bounds__(256) softmax_kernel()
{
    __shared__ float sred[8];
    const float4* r4 = (const float4*)(g_S + (size_t)blockIdx.x * NSEQ);
    uint2* o4 = (uint2*)(g_P + (size_t)blockIdx.x * NSEQ);
    const int tid = threadIdx.x;

    const float4 a = r4[tid];
    const float4 bq = r4[256 + tid];
    float v[8] = {a.x, a.y, a.z, a.w, bq.x, bq.y, bq.z, bq.w};

    float m = v[0];
#pragma unroll
    for (int t = 1; t < 8; t++) m = fmaxf(m, v[t]);
#pragma unroll
    for (int off = 16; off > 0; off >>= 1)
        m = fmaxf(m, __shfl_xor_sync(0xffffffffu, m, off));
    if ((tid & 31) == 0) sred[tid >> 5] = m;
    __syncthreads();
    m = sred[0];
#pragma unroll
    for (int w = 1; w < 8; w++) m = fmaxf(m, sred[w]);

    float s = 0.f;
#pragma unroll
    for (int t = 0; t < 8; t++) {
        v[t] = __expf(v[t] - m);
        s += v[t];
    }
#pragma unroll
    for (int off = 16; off > 0; off >>= 1)
        s += __shfl_xor_sync(0xffffffffu, s, off);
    __syncthreads();
    if ((tid & 31) == 0) sred[tid >> 5] = s;
    __syncthreads();
    s = 0.f;
#pragma unroll
    for (int w = 0; w < 8; w++) s += sred[w];
    const float inv = 1.0f / s;

    o4[tid]       = make_uint2(pk(v[0] * inv, v[1] * inv), pk(v[2] * inv, v[3] * inv));
    o4[256 + tid] = make_uint2(pk(v[4] * inv, v[5] * inv), pk(v[6] * inv, v[7] * inv));
}

// ---------------------------------------------------------------------------
// Kernel 5: O = P @ Vt^T (NT). grid (DIM/256=2, 16, 8)
// ---------------------------------------------------------------------------
__global__ void __launch_bounds__(256, 1) av_tc(float* __restrict__ out)
{
    const int b = blockIdx.z;
    float acc[4][8][4];
    ACC_INIT(acc);
    gemm_nt_256(g_P   + (size_t)b * NSEQ * NSEQ,
                g_Vth + (size_t)b * DIM * NSEQ,
                NSEQ, NSEQ, NSEQ / KT, acc);

    float* C = out + (size_t)b * NSEQ * DIM;
    const int lane = threadIdx.x & 31;
    const int warp = threadIdx.x >> 5;
    const int wm = (warp & 1) * 64;
    const int wn = (warp >> 1) * 64;
    const int grp = lane >> 2, tig = lane & 3;
#pragma unroll
    for (int i = 0; i < 4; i++) {
        const int row = blockIdx.y * 128 + wm + i * 16 + grp;
#pragma unroll
        for (int j = 0; j < 8; j++) {
            const int col = blockIdx.x * 256 + wn + j * 8 + 2 * tig;
            *(float2*)&C[(size_t)row * DIM + col] =
                make_float2(acc[i][j][0], acc[i][j][1]);
            *(float2*)&C[(size_t)(row + 8) * DIM + col] =
                make_float2(acc[i][j][2], acc[i][j][3]);
        }
    }
}

// ---------------------------------------------------------------------------
// Launch
// ---------------------------------------------------------------------------
extern "C" void kernel_launch(void* const* d_in, const int* in_sizes, int n_in,
                              void* d_out, int out_size)
{
    const float* X    = (const float*)d_in[0];
    const int*   mask = (const int*)  d_in[1];
    const float* Wk   = (const float*)d_in[2];
    const float* bk   = (const float*)d_in[3];
    const float* Wq   = (const float*)d_in[4];
    const float* bq   = (const float*)d_in[5];
    const float* Wv   = (const float*)d_in[6];
    const float* bv   = (const float*)d_in[7];
    float* out = (float*)d_out;

    cudaFuncSetAttribute(proj_tc,   cudaFuncAttributeMaxDynamicSharedMemorySize, DYN_SMEM);
    cudaFuncSetAttribute(scores_tc, cudaFuncAttributeMaxDynamicSharedMemorySize, DYN_SMEM);
    cudaFuncSetAttribute(av_tc,     cudaFuncAttributeMaxDynamicSharedMemorySize, DYN_SMEM);

    __half* x_h;
    cudaGetSymbolAddress((void**)&x_h, g_Xh);

    const int nx4 = MTOT * DIM / 4;
    cvt_kernel<<<(nx4 + 255) / 256, 256>>>(X, x_h, nx4);
    cvtw_kernel<<<dim3(DIM * DIM / 4 / 256, 3), 256>>>(Wq, Wk, Wv);

    proj_tc   <<<dim3(DIM / 256, MTOT / 128, 3), 256, DYN_SMEM>>>(bq, bk, bv);
    scores_tc <<<dim3(NSEQ / 256, NSEQ / 128, BB), 256, DYN_SMEM>>>(mask);
    softmax_kernel<<<MTOT, 256>>>();
    av_tc     <<<dim3(DIM / 256, NSEQ / 128, BB), 256, DYN_SMEM>>>(out);
}

// round 17
// speedup vs baseline: 1.1744x; 1.1744x over previous
#include <cuda_runtime.h>
#include <cuda_fp16.h>
#include <math.h>
#include <stdint.h>

#define BB 8
#define NSEQ 2048
#define DIM 512
#define MTOT (BB * NSEQ)

// Scratch (alloc-free rule: __device__ globals)
__device__ __half g_Xh[(size_t)MTOT * DIM];
__device__ __half g_Wh[(size_t)3 * DIM * DIM];
__device__ __half g_Qh[(size_t)MTOT * DIM];
__device__ __half g_Kh[(size_t)MTOT * DIM];
__device__ __half g_Vth[(size_t)BB * DIM * NSEQ];   // [b][d][n]
__device__ float  g_S[(size_t)BB * NSEQ * NSEQ];    // fp32 logits
__device__ __half g_P[(size_t)BB * NSEQ * NSEQ];    // fp16 probabilities

// ---------------------------------------------------------------------------
// helpers
// ---------------------------------------------------------------------------
__device__ __forceinline__ unsigned pk(float a, float b) {
    __half2 h = __floats2half2_rn(a, b);
    return *reinterpret_cast<unsigned*>(&h);
}
__device__ __forceinline__ uint32_t smem_u32(const void* p) {
    uint32_t a;
    asm("{ .reg .u64 t; cvta.to.shared.u64 t, %1; cvt.u32.u64 %0, t; }" : "=r"(a) : "l"(p));
    return a;
}
__device__ __forceinline__ void mma16(float c[4],
                                      unsigned a0, unsigned a1, unsigned a2, unsigned a3,
                                      unsigned b0, unsigned b1) {
    asm volatile(
        "mma.sync.aligned.m16n8k16.row.col.f32.f16.f16.f32 "
        "{%0,%1,%2,%3}, {%4,%5,%6,%7}, {%8,%9}, {%0,%1,%2,%3};"
        : "+f"(c[0]), "+f"(c[1]), "+f"(c[2]), "+f"(c[3])
        : "r"(a0), "r"(a1), "r"(a2), "r"(a3), "r"(b0), "r"(b1));
}
__device__ __forceinline__ void ldm_x4(unsigned& r0, unsigned& r1, unsigned& r2, unsigned& r3,
                                       uint32_t addr) {
    asm volatile("ldmatrix.sync.aligned.m8n8.x4.shared.b16 {%0,%1,%2,%3}, [%4];"
        : "=r"(r0), "=r"(r1), "=r"(r2), "=r"(r3) : "r"(addr));
}
__device__ __forceinline__ void cpa16(uint32_t dst, const void* src) {
    asm volatile("cp.async.ca.shared.global [%0], [%1], 16;" :: "r"(dst), "l"(src));
}
#define CP_COMMIT() asm volatile("cp.async.commit_group;" ::: "memory")
template<int N>
__device__ __forceinline__ void cp_wait() {
    asm volatile("cp.async.wait_group %0;" :: "n"(N) : "memory");
}

// ---------------------------------------------------------------------------
// GEMM NT: C(128x256 tile at (by,bx)) = A[M,K] * B[N,K]^T, fp16 in, fp32 acc.
// K_TILE = 64 halves -> 128B data rows padded to 144B (36 words).
// 3-stage cp.async pipeline, fill issued BEFORE cp_wait (R15-proven), two
// syncs per k-tile. NEW: register double-buffered fragments — ldmatrix for
// k-step ks+1 issues before the MMA burst of ks, hiding LDS latency.
// Warps 2(M) x 4(N), warp tile 64x64.
// ---------------------------------------------------------------------------
#define KT 64
#define ROWB 144
#define STAGE_BYTES (384 * ROWB)            // 55296
#define NSTAGE 3
#define DYN_SMEM (NSTAGE * STAGE_BYTES)     // 165888

__device__ __forceinline__ void fill_stage(uint32_t sb,
                                           const __half* __restrict__ A,
                                           const __half* __restrict__ B,
                                           int lda, int ldb, int tid)
{
#pragma unroll
    for (int it = 0; it < 4; it++) {           // A: 128 rows x 8 chunks
        const int cid = it * 256 + tid;
        const int row = cid >> 3, c = cid & 7;
        cpa16(sb + row * ROWB + c * 16, A + (size_t)row * lda + c * 8);
    }
#pragma unroll
    for (int it = 0; it < 8; it++) {           // B: 256 rows x 8 chunks
        const int cid = it * 256 + tid;
        const int row = cid >> 3, c = cid & 7;
        cpa16(sb + 128 * ROWB + row * ROWB + c * 16, B + (size_t)row * ldb + c * 8);
    }
}

// load one k-step's fragments (A 64x16, B 64x16 per warp)
__device__ __forceinline__ void load_frags(unsigned af[4][4], unsigned bf[8][2],
                                           uint32_t ab, uint32_t bb,
                                           int wm, int wn, uint32_t lro, int ks)
{
#pragma unroll
    for (int i = 0; i < 4; i++)
        ldm_x4(af[i][0], af[i][1], af[i][2], af[i][3],
               ab + (wm + i * 16) * ROWB + ks * 32 + lro);
#pragma unroll
    for (int jj = 0; jj < 4; jj++)
        ldm_x4(bf[2 * jj][0], bf[2 * jj + 1][0], bf[2 * jj][1], bf[2 * jj + 1][1],
               bb + (wn + jj * 16) * ROWB + ks * 32 + lro);
}

__device__ __forceinline__ void gemm_nt_256(const __half* __restrict__ A,
                                            const __half* __restrict__ B,
                                            int lda, int ldb, int ktiles,
                                            float acc[4][8][4])
{
    extern __shared__ unsigned smdyn[];
    const uint32_t sb = smem_u32(smdyn);
    const int tid = threadIdx.x;

    A += (size_t)(blockIdx.y * 128) * lda;
    B += (size_t)(blockIdx.x * 256) * ldb;

    fill_stage(sb, A, B, lda, ldb, tid);
    CP_COMMIT();
    if (ktiles > 1) {
        fill_stage(sb + STAGE_BYTES, A + KT, B + KT, lda, ldb, tid);
        CP_COMMIT();
    }

    const int lane = tid & 31;
    const int warp = tid >> 5;
    const int wm = (warp & 1) * 64;
    const int wn = (warp >> 1) * 64;
    const uint32_t lro = (uint32_t)((lane & 15) * ROWB + (lane >> 4) * 16);

#pragma unroll 1
    for (int kt = 0; kt < ktiles; kt++) {
        if (kt + 2 < ktiles) {
            fill_stage(sb + ((kt + 2) % NSTAGE) * STAGE_BYTES,
                       A + (size_t)(kt + 2) * KT, B + (size_t)(kt + 2) * KT,
                       lda, ldb, tid);
            CP_COMMIT();
            cp_wait<2>();
        } else if (kt + 1 < ktiles) {
            cp_wait<1>();
        } else {
            cp_wait<0>();
        }
        __syncthreads();          // stage kt visible to all warps

        const uint32_t ab = sb + (kt % NSTAGE) * STAGE_BYTES;
        const uint32_t bb = ab + 128 * ROWB;

        unsigned af[2][4][4], bf[2][8][2];
        load_frags(af[0], bf[0], ab, bb, wm, wn, lro, 0);
#pragma unroll
        for (int ks = 0; ks < 4; ks++) {
            const int cur = ks & 1;
            if (ks < 3)
                load_frags(af[cur ^ 1], bf[cur ^ 1], ab, bb, wm, wn, lro, ks + 1);
#pragma unroll
            for (int i = 0; i < 4; i++)
#pragma unroll
                for (int j = 0; j < 8; j++)
                    mma16(acc[i][j], af[cur][i][0], af[cur][i][1],
                          af[cur][i][2], af[cur][i][3],
                          bf[cur][j][0], bf[cur][j][1]);
        }
        __syncthreads();          // all warps done reading stage kt (WAR for refill)
    }
}

#define ACC_INIT(acc) \
    _Pragma("unroll") for (int i = 0; i < 4; i++) \
    _Pragma("unroll") for (int j = 0; j < 8; j++) \
    _Pragma("unroll") for (int v = 0; v < 4; v++) acc[i][j][v] = 0.f;

// ---------------------------------------------------------------------------
// Kernel 0a: fp32 -> fp16 convert (X)
// ---------------------------------------------------------------------------
__global__ void __launch_bounds__(256) cvt_kernel(const float* __restrict__ src,
                                                  __half* __restrict__ dst, int n4)
{
    const int i = blockIdx.x * 256 + threadIdx.x;
    if (i < n4) {
        const float4 f = ((const float4*)src)[i];
        ((uint2*)dst)[i] = make_uint2(pk(f.x, f.y), pk(f.z, f.w));
    }
}

// Kernel 0b: convert 3 weight matrices in one launch. grid (256, 3)
__global__ void __launch_bounds__(256) cvtw_kernel(const float* __restrict__ wq,
                                                   const float* __restrict__ wk,
                                                   const float* __restrict__ wv)
{
    const float* src = (blockIdx.y == 0) ? wq : (blockIdx.y == 1) ? wk : wv;
    __half* dst = g_Wh + (size_t)blockIdx.y * DIM * DIM;
    const int i = blockIdx.x * 256 + threadIdx.x;   // n4 = 65536 exactly
    const float4 f = ((const float4*)src)[i];
    ((uint2*)dst)[i] = make_uint2(pk(f.x, f.y), pk(f.z, f.w));
}

// ---------------------------------------------------------------------------
// Kernel 1: QKV projections. grid (DIM/256=2, MTOT/128=128, 3)
// z==2 (V): result is staged in smem and written TRANSPOSED to g_Vth only.
// ---------------------------------------------------------------------------
__global__ void __launch_bounds__(256, 1) proj_tc(
    const float* __restrict__ bq, const float* __restrict__ bk,
    const float* __restrict__ bv)
{
    const float* bias = (blockIdx.z == 0) ? bq : (blockIdx.z == 1) ? bk : bv;

    float acc[4][8][4];
    ACC_INIT(acc);
    gemm_nt_256(g_Xh, g_Wh + (size_t)blockIdx.z * DIM * DIM, DIM, DIM, DIM / KT, acc);

    const int tid  = threadIdx.x;
    const int lane = tid & 31;
    const int warp = tid >> 5;
    const int wm = (warp & 1) * 64;
    const int wn = (warp >> 1) * 64;
    const int grp = lane >> 2, tig = lane & 3;

    if (blockIdx.z < 2) {
        __half* C = (blockIdx.z == 0) ? g_Qh : g_Kh;
#pragma unroll
        for (int i = 0; i < 4; i++) {
            const int row = blockIdx.y * 128 + wm + i * 16 + grp;
#pragma unroll
            for (int j = 0; j < 8; j++) {
                const int col = blockIdx.x * 256 + wn + j * 8 + 2 * tig;
                const float b0 = bias[col], b1 = bias[col + 1];
                *(unsigned*)&C[(size_t)row * DIM + col] =
                    pk(acc[i][j][0] + b0, acc[i][j][1] + b1);
                *(unsigned*)&C[(size_t)(row + 8) * DIM + col] =
                    pk(acc[i][j][2] + b0, acc[i][j][3] + b1);
            }
        }
    } else {
        // V: transpose through smem (mainloop ended with __syncthreads)
        extern __shared__ unsigned smdyn[];
        __half* Ts = reinterpret_cast<__half*>(smdyn);   // [256 d][136 n-stride]
        const int b  = blockIdx.y / 16;                  // batch (16 y-blocks per batch)
        const int n0 = (blockIdx.y % 16) * 128;
        const int d0 = blockIdx.x * 256;
#pragma unroll
        for (int i = 0; i < 4; i++) {
            const int row = wm + i * 16 + grp;           // local n: 0..127
#pragma unroll
            for (int j = 0; j < 8; j++) {
                const int col = wn + j * 8 + 2 * tig;    // local d: 0..255
                const float b0 = bias[d0 + col], b1 = bias[d0 + col + 1];
                Ts[(col)     * 136 + row]     = __float2half(acc[i][j][0] + b0);
                Ts[(col + 1) * 136 + row]     = __float2half(acc[i][j][1] + b1);
                Ts[(col)     * 136 + row + 8] = __float2half(acc[i][j][2] + b0);
                Ts[(col + 1) * 136 + row + 8] = __float2half(acc[i][j][3] + b1);
            }
        }
        __syncthreads();
        // coalesced write-out: thread t owns d-row t (128 halves = 16 x uint4)
        __half* dst = g_Vth + (size_t)b * DIM * NSEQ + (size_t)(d0 + tid) * NSEQ + n0;
        const uint4* srow = reinterpret_cast<const uint4*>(Ts + (size_t)tid * 136);
#pragma unroll
        for (int i = 0; i < 16; i++)
            reinterpret_cast<uint4*>(dst)[i] = srow[i];
    }
}

// ---------------------------------------------------------------------------
// Kernel 3: scores = mask(QK^T / sqrt(D)) -> fp32 S. grid (8, 16, 8)
// ---------------------------------------------------------------------------
__global__ void __launch_bounds__(256, 1) scores_tc(const int* __restrict__ mask)
{
    const int b = blockIdx.z;
    float acc[4][8][4];
    ACC_INIT(acc);
    gemm_nt_256(g_Qh + (size_t)b * NSEQ * DIM, g_Kh + (size_t)b * NSEQ * DIM,
                DIM, DIM, DIM / KT, acc);

    const float scale = 0.04419417382415922f;  // 1/sqrt(512)
    const int lane = threadIdx.x & 31;
    const int warp = threadIdx.x >> 5;
    const int wm = (warp & 1) * 64;
    const int wn = (warp >> 1) * 64;
    const int grp = lane >> 2, tig = lane & 3;
    const int* mrow = mask + (size_t)b * NSEQ;
    float* C = g_S + (size_t)b * NSEQ * NSEQ;
#pragma unroll
    for (int i = 0; i < 4; i++) {
        const int row = blockIdx.y * 128 + wm + i * 16 + grp;
#pragma unroll
        for (int j = 0; j < 8; j++) {
            const int col = blockIdx.x * 256 + wn + j * 8 + 2 * tig;
            const bool k0 = (mrow[col] == 0);
            const bool k1 = (mrow[col + 1] == 0);
            const float v0 = k0 ? -1e9f : acc[i][j][0] * scale;
            const float v1 = k1 ? -1e9f : acc[i][j][1] * scale;
            const float v2 = k0 ? -1e9f : acc[i][j][2] * scale;
            const float v3 = k1 ? -1e9f : acc[i][j][3] * scale;
            *(float2*)&C[(size_t)row * NSEQ + col]       = make_float2(v0, v1);
            *(float2*)&C[(size_t)(row + 8) * NSEQ + col] = make_float2(v2, v3);
        }
    }
}

// ---------------------------------------------------------------------------
// Kernel 4: row softmax fp32 S -> fp16 P. One block (256 thr) per row. float4 IO.
// ---------------------------------------------------------------------------
__global__ void __launch_bounds__(256) softmax_kernel()
{
    __shared__ float sred[8];
    const float4* r4 = (const float4*)(g_S + (size_t)blockIdx.x * NSEQ);
    uint2* o4 = (uint2*)(g_P + (size_t)blockIdx.x * NSEQ);
    const int tid = threadIdx.x;

    const float4 a = r4[tid];
    const float4 bq = r4[256 + tid];
    float v[8] = {a.x, a.y, a.z, a.w, bq.x, bq.y, bq.z, bq.w};

    float m = v[0];
#pragma unroll
    for (int t = 1; t < 8; t++) m = fmaxf(m, v[t]);
#pragma unroll
    for (int off = 16; off > 0; off >>= 1)
        m = fmaxf(m, __shfl_xor_sync(0xffffffffu, m, off));
    if ((tid & 31) == 0) sred[tid >> 5] = m;
    __syncthreads();
    m = sred[0];
#pragma unroll
    for (int w = 1; w < 8; w++) m = fmaxf(m, sred[w]);

    float s = 0.f;
#pragma unroll
    for (int t = 0; t < 8; t++) {
        v[t] = __expf(v[t] - m);
        s += v[t];
    }
#pragma unroll
    for (int off = 16; off > 0; off >>= 1)
        s += __shfl_xor_sync(0xffffffffu, s, off);
    __syncthreads();
    if ((tid & 31) == 0) sred[tid >> 5] = s;
    __syncthreads();
    s = 0.f;
#pragma unroll
    for (int w = 0; w < 8; w++) s += sred[w];
    const float inv = 1.0f / s;

    o4[tid]       = make_uint2(pk(v[0] * inv, v[1] * inv), pk(v[2] * inv, v[3] * inv));
    o4[256 + tid] = make_uint2(pk(v[4] * inv, v[5] * inv), pk(v[6] * inv, v[7] * inv));
}

// ---------------------------------------------------------------------------
// Kernel 5: O = P @ Vt^T (NT). grid (DIM/256=2, 16, 8)
// ---------------------------------------------------------------------------
__global__ void __launch_bounds__(256, 1) av_tc(float* __restrict__ out)
{
    const int b = blockIdx.z;
    float acc[4][8][4];
    ACC_INIT(acc);
    gemm_nt_256(g_P   + (size_t)b * NSEQ * NSEQ,
                g_Vth + (size_t)b * DIM * NSEQ,
                NSEQ, NSEQ, NSEQ / KT, acc);

    float* C = out + (size_t)b * NSEQ * DIM;
    const int lane = threadIdx.x & 31;
    const int warp = threadIdx.x >> 5;
    const int wm = (warp & 1) * 64;
    const int wn = (warp >> 1) * 64;
    const int grp = lane >> 2, tig = lane & 3;
#pragma unroll
    for (int i = 0; i < 4; i++) {
        const int row = blockIdx.y * 128 + wm + i * 16 + grp;
#pragma unroll
        for (int j = 0; j < 8; j++) {
            const int col = blockIdx.x * 256 + wn + j * 8 + 2 * tig;
            *(float2*)&C[(size_t)row * DIM + col] =
                make_float2(acc[i][j][0], acc[i][j][1]);
            *(float2*)&C[(size_t)(row + 8) * DIM + col] =
                make_float2(acc[i][j][2], acc[i][j][3]);
        }
    }
}

// ---------------------------------------------------------------------------
// Launch
// ---------------------------------------------------------------------------
extern "C" void kernel_launch(void* const* d_in, const int* in_sizes, int n_in,
                              void* d_out, int out_size)
{
    const float* X    = (const float*)d_in[0];
    const int*   mask = (const int*)  d_in[1];
    const float* Wk   = (const float*)d_in[2];
    const float* bk   = (const float*)d_in[3];
    const float* Wq   = (const float*)d_in[4];
    const float* bq   = (const float*)d_in[5];
    const float* Wv   = (const float*)d_in[6];
    const float* bv   = (const float*)d_in[7];
    float* out = (float*)d_out;

    cudaFuncSetAttribute(proj_tc,   cudaFuncAttributeMaxDynamicSharedMemorySize, DYN_SMEM);
    cudaFuncSetAttribute(scores_tc, cudaFuncAttributeMaxDynamicSharedMemorySize, DYN_SMEM);
    cudaFuncSetAttribute(av_tc,     cudaFuncAttributeMaxDynamicSharedMemorySize, DYN_SMEM);

    __half* x_h;
    cudaGetSymbolAddress((void**)&x_h, g_Xh);

    const int nx4 = MTOT * DIM / 4;
    cvt_kernel<<<(nx4 + 255) / 256, 256>>>(X, x_h, nx4);
    cvtw_kernel<<<dim3(DIM * DIM / 4 / 256, 3), 256>>>(Wq, Wk, Wv);

    proj_tc   <<<dim3(DIM / 256, MTOT / 128, 3), 256, DYN_SMEM>>>(bq, bk, bv);
    scores_tc <<<dim3(NSEQ / 256, NSEQ / 128, BB), 256, DYN_SMEM>>>(mask);
    softmax_kernel<<<MTOT, 256>>>();
    av_tc     <<<dim3(DIM / 256, NSEQ / 128, BB), 256, DYN_SMEM>>>(out);
}